// round 11
// baseline (speedup 1.0000x reference)
#include <cuda_runtime.h>
#include <cuda_bf16.h>
#include <math.h>

#define Bc   32
#define Tc   256
#define Fc   32
#define HIDc 128
#define ZW   640
#define Vc   101
#define LBLc 32
#define NEGF (-1e30f)

#define NCTA 128            // 16 jkb x 4 bg x 2 cgrp
#define NTHR 128
#define NKK  8
#define NCOLS 40            // 8 kk x 5 gates

// Padded strides (bytes / floats)
#define ASTR 528            // 256 bf16 = 512B + 16B pad (33 x 16B chunks)
#define ZSTR 41             // z row stride in floats (odd -> conflict-free)

// smem byte offsets
#define SM_Z0   0                    // 40 x {wx, bias} = 320B (pad 512)
#define SM_C    512                  // 128 x 8 floats = 4096
#define SM_Z    4608                 // 128 x 41 floats = 20992
#define SM_A_HI 25600                // 128 x 528 = 67584
#define SM_A_LO 93184
#define SM_B_HI 160768               // 40 x 528 = 21120
#define SM_B_LO 181888
#define SMEM_TOTAL 203008

__device__ __align__(16) unsigned short g_hhi[2][Fc][Bc][HIDc];
__device__ __align__(16) unsigned short g_hlo[2][Fc][Bc][HIDc];
__device__ __align__(16) float g_c[2][Fc][Bc][HIDc];
__device__ __align__(16) float g_feat[Bc][Tc][HIDc];
__device__ __align__(16) float g_logp[Bc][Tc][Vc];
__device__ unsigned g_cnt4[4 * 32];
__device__ unsigned g_gen4[4 * 32];

__device__ __forceinline__ float fsig(float x) {
    return __fdividef(1.0f, 1.0f + __expf(-x));
}
__device__ __forceinline__ float ftanh(float x) {
    return 1.0f - __fdividef(2.0f, __expf(2.0f * x) + 1.0f);
}
__device__ __forceinline__ unsigned smem_u32(const void* p) {
    unsigned a;
    asm("{ .reg .u64 t; cvta.to.shared.u64 t, %1; cvt.u32.u64 %0, t; }" : "=r"(a) : "l"(p));
    return a;
}

__device__ __forceinline__ void ldsm4(unsigned& r0, unsigned& r1, unsigned& r2,
                                      unsigned& r3, unsigned addr) {
    asm volatile("ldmatrix.sync.aligned.m8n8.x4.shared.b16 {%0,%1,%2,%3}, [%4];"
                 : "=r"(r0), "=r"(r1), "=r"(r2), "=r"(r3) : "r"(addr));
}
__device__ __forceinline__ void ldsm2(unsigned& r0, unsigned& r1, unsigned addr) {
    asm volatile("ldmatrix.sync.aligned.m8n8.x2.shared.b16 {%0,%1}, [%2];"
                 : "=r"(r0), "=r"(r1) : "r"(addr));
}
__device__ __forceinline__ void mma16816(float* d, const unsigned* a, const unsigned* b) {
    asm volatile("mma.sync.aligned.m16n8k16.row.col.f32.bf16.bf16.f32 "
                 "{%0,%1,%2,%3}, {%4,%5,%6,%7}, {%8,%9}, {%0,%1,%2,%3};"
                 : "+f"(d[0]), "+f"(d[1]), "+f"(d[2]), "+f"(d[3])
                 : "r"(a[0]), "r"(a[1]), "r"(a[2]), "r"(a[3]), "r"(b[0]), "r"(b[1]));
}

__global__ void init_kernel() {
    const int nh = 2 * Fc * Bc * HIDc;
    unsigned short* p1 = &g_hhi[0][0][0][0];
    unsigned short* p2 = &g_hlo[0][0][0][0];
    float* pc = &g_c[0][0][0][0];
    for (int i = blockIdx.x * blockDim.x + threadIdx.x; i < nh;
         i += gridDim.x * blockDim.x) { p1[i] = 0; p2[i] = 0; pc[i] = 0.f; }
    const int nf = Bc * Tc * HIDc;
    float* pf = &g_feat[0][0][0];
    for (int i = blockIdx.x * blockDim.x + threadIdx.x; i < nf;
         i += gridDim.x * blockDim.x) pf[i] = 0.f;
    if (blockIdx.x == 0 && threadIdx.x < 4 * 32) {
        g_cnt4[threadIdx.x] = 0u; g_gen4[threadIdx.x] = 0u;
    }
}

__device__ __forceinline__ void gbar(int it, int bg) {
    __syncthreads();
    if (threadIdx.x == 0) {
        unsigned* cnt = &g_cnt4[bg * 32];
        unsigned* gen = &g_gen4[bg * 32];
        const unsigned target = (unsigned)(it + 1);
        unsigned old;
        asm volatile("atom.acq_rel.gpu.global.add.u32 %0, [%1], %2;"
                     : "=r"(old) : "l"(cnt), "r"(1u) : "memory");
        if (old == target * 32u - 1u) {
            asm volatile("st.release.gpu.global.u32 [%0], %1;"
                         :: "l"(gen), "r"(target) : "memory");
        } else {
            unsigned cur;
            do {
                asm volatile("ld.acquire.gpu.global.u32 %0, [%1];"
                             : "=r"(cur) : "l"(gen) : "memory");
            } while (cur < target);
        }
    }
    __syncthreads();
}

// ---------------------------------------------------------------------------
// Persistent HMMA MDLSTM wavefront.
// CTA: z[128 rows, 40 cols] = A[128,256] x B[40,256]^T, split-bf16 3-pass via
// mma.sync.m16n8k16. Warp w owns rows [32w, 32w+32). D -> smem z buffer ->
// per-thread (row = tid) epilogue with all 40 gate preacts.
// ---------------------------------------------------------------------------
__global__ __launch_bounds__(NTHR, 1)
void mdlstm_persist(const float* __restrict__ X,
                    const float* __restrict__ Wx,
                    const float* __restrict__ Wh1,
                    const float* __restrict__ Wh2,
                    const float* __restrict__ bias)
{
    extern __shared__ char smem[];
    const unsigned sm = smem_u32(smem);
    const int tid  = threadIdx.x;
    const int wid  = tid >> 5;
    const int lane = tid & 31;
    const int bx   = blockIdx.x;
    const int jkb  = bx & 15;
    const int bg   = (bx >> 4) & 3;
    const int cgrp = bx >> 6;
    const int kk0  = jkb * NKK;

    // One-time: B weights (40 cols x 256 k) into padded rows, split hi/lo.
    for (int i = tid; i < NCOLS * 256; i += NTHR) {
        int n = i >> 8, k = i & 255;
        int g = n % 5, kkl = n / 5;
        int gcol = g * HIDc + kk0 + kkl;
        float v = (k < 128) ? Wh1[k * ZW + gcol] : Wh2[(k - 128) * ZW + gcol];
        __nv_bfloat16 hi = __float2bfloat16(v);
        __nv_bfloat16 lo = __float2bfloat16(v - __bfloat162float(hi));
        *(unsigned short*)(smem + SM_B_HI + n * ASTR + k * 2) = __bfloat16_as_ushort(hi);
        *(unsigned short*)(smem + SM_B_LO + n * ASTR + k * 2) = __bfloat16_as_ushort(lo);
    }
    if (tid < NCOLS) {
        int g = tid % 5, kkl = tid / 5;
        int gcol = g * HIDc + kk0 + kkl;
        ((float*)(smem + SM_Z0))[tid * 2]     = Wx[gcol];
        ((float*)(smem + SM_Z0))[tid * 2 + 1] = bias[gcol];
    }

    const int bb = bg * 8 + (tid & 7);
    const int slot = cgrp * 16 + (tid >> 3);
    float c_reg[NKK];
#pragma unroll
    for (int q = 0; q < NKK; q++) c_reg[q] = 0.f;

    // ldmatrix per-lane byte offsets
    const unsigned aoff0 = (unsigned)(wid * 32 + (lane & 15)) * ASTR + (unsigned)(lane >> 4) * 16;
    const unsigned aoff1 = aoff0 + 16 * ASTR;
    const unsigned boff  = (unsigned)(lane & 7) * ASTR + (unsigned)((lane >> 3) & 1) * 16;

    float* s_c  = (float*)(smem + SM_C);
    float* s_z  = (float*)(smem + SM_Z);
    const float* s_z0 = (const float*)(smem + SM_Z0);
    __syncthreads();

    for (int d = 0; d < Tc + Fc - 1; d++) {
        const int h_lo = (d > Tc - 1) ? d - (Tc - 1) : 0;
        const int h_hi = (d < Fc - 1) ? d : (Fc - 1);
        const int rd = (d + 1) & 1, wr = d & 1;
        const bool regB = (d > Tc - 1);
        const int H = h_lo + slot;
        const bool val = (H <= h_hi) && (slot <= d);
        const int W = d - H;

        // boundary c prefetch (cross-CTA cell neighbors)
        float cb[NKK];
#pragma unroll
        for (int q = 0; q < NKK; q++) cb[q] = 0.f;
        if (!regB) {
            if (tid < 8 && val && H > 0) {
                float4 a = __ldcg((const float4*)&g_c[rd][H - 1][bb][kk0]);
                float4 b = __ldcg((const float4*)&g_c[rd][H - 1][bb][kk0 + 4]);
                cb[0]=a.x; cb[1]=a.y; cb[2]=a.z; cb[3]=a.w;
                cb[4]=b.x; cb[5]=b.y; cb[6]=b.z; cb[7]=b.w;
            }
        } else {
            if (tid >= 120 && val) {
                float4 a = __ldcg((const float4*)&g_c[rd][H][bb][kk0]);
                float4 b = __ldcg((const float4*)&g_c[rd][H][bb][kk0 + 4]);
                cb[0]=a.x; cb[1]=a.y; cb[2]=a.z; cb[3]=a.w;
                cb[4]=b.x; cb[5]=b.y; cb[6]=b.z; cb[7]=b.w;
            }
        }
        const float xv = val ? __ldg(&X[bb * (Tc * Fc) + W * Fc + H]) : 0.f;

        // Stage A (hi, lo): row r: cols k<128 = h[H_r], k>=128 = h[H_r - 1].
        for (int i = tid; i < 8192; i += NTHR) {
            int tile = i >> 12;
            int c = i & 4095;
            int r = c >> 5;
            int ck = c & 31;
            int hs = h_lo + cgrp * 16 + (r >> 3) - ((ck < 16) ? 0 : 1);
            int bbs = bg * 8 + (r & 7);
            uint4 v = make_uint4(0u, 0u, 0u, 0u);
            if (hs >= 0 && hs < Fc) {
                const unsigned short* src =
                    tile ? &g_hlo[rd][hs][bbs][0] : &g_hhi[rd][hs][bbs][0];
                v = __ldcg((const uint4*)(src + (ck & 15) * 8));
            }
            *(uint4*)(smem + (tile ? SM_A_LO : SM_A_HI) + r * ASTR + ck * 16) = v;
        }
        __syncthreads();

        // ----- GEMM: 3-pass split bf16 -----
        float acc[2][5][4];
#pragma unroll
        for (int m = 0; m < 2; m++)
#pragma unroll
            for (int nt = 0; nt < 5; nt++)
#pragma unroll
                for (int e = 0; e < 4; e++) acc[m][nt][e] = 0.f;

#pragma unroll 2
        for (int kt = 0; kt < 16; kt++) {
            const unsigned kb = (unsigned)kt * 32u;
            unsigned ah0[4], ah1[4], al0[4], al1[4];
            ldsm4(ah0[0], ah0[1], ah0[2], ah0[3], sm + SM_A_HI + aoff0 + kb);
            ldsm4(ah1[0], ah1[1], ah1[2], ah1[3], sm + SM_A_HI + aoff1 + kb);
            ldsm4(al0[0], al0[1], al0[2], al0[3], sm + SM_A_LO + aoff0 + kb);
            ldsm4(al1[0], al1[1], al1[2], al1[3], sm + SM_A_LO + aoff1 + kb);
            unsigned bh[5][2], bl[5][2];
#pragma unroll
            for (int nt = 0; nt < 5; nt++) {
                ldsm2(bh[nt][0], bh[nt][1], sm + SM_B_HI + boff + nt * (8 * ASTR) + kb);
                ldsm2(bl[nt][0], bl[nt][1], sm + SM_B_LO + boff + nt * (8 * ASTR) + kb);
            }
#pragma unroll
            for (int nt = 0; nt < 5; nt++) {
                mma16816(acc[0][nt], ah0, bh[nt]);
                mma16816(acc[1][nt], ah1, bh[nt]);
            }
#pragma unroll
            for (int nt = 0; nt < 5; nt++) {
                mma16816(acc[0][nt], al0, bh[nt]);
                mma16816(acc[1][nt], al1, bh[nt]);
            }
#pragma unroll
            for (int nt = 0; nt < 5; nt++) {
                mma16816(acc[0][nt], ah0, bl[nt]);
                mma16816(acc[1][nt], ah1, bl[nt]);
            }
        }

        // D frags -> z smem
        {
            const int rbase = wid * 32 + (lane >> 2);
            const int cbase = (lane & 3) * 2;
#pragma unroll
            for (int m = 0; m < 2; m++)
#pragma unroll
                for (int nt = 0; nt < 5; nt++) {
                    int r0 = rbase + m * 16;
                    int cc = nt * 8 + cbase;
                    s_z[r0 * ZSTR + cc]           = acc[m][nt][0];
                    s_z[r0 * ZSTR + cc + 1]       = acc[m][nt][1];
                    s_z[(r0 + 8) * ZSTR + cc]     = acc[m][nt][2];
                    s_z[(r0 + 8) * ZSTR + cc + 1] = acc[m][nt][3];
                }
        }
        __syncthreads();

        // neighbor c from previous diagonal's s_c
        float coth[NKK];
#pragma unroll
        for (int q = 0; q < NKK; q++) {
            if (!regB) coth[q] = (tid >= 8)  ? s_c[(tid - 8) * NKK + q] : cb[q];
            else       coth[q] = (tid < 120) ? s_c[(tid + 8) * NKK + q] : cb[q];
        }
        __syncthreads();

        float hval[NKK];
#pragma unroll
        for (int q = 0; q < NKK; q++) {
            float z[5];
#pragma unroll
            for (int g = 0; g < 5; g++) {
                int n = q * 5 + g;
                z[g] = s_z[tid * ZSTR + n] + fmaf(xv, s_z0[n * 2], s_z0[n * 2 + 1]);
            }
            float cl = regB ? coth[q] : c_reg[q];
            float cu = regB ? c_reg[q] : coth[q];
            float c = fsig(z[2]) * cl + fsig(z[3]) * cu + fsig(z[0]) * ftanh(z[1]);
            float h = fsig(z[4]) * ftanh(c);
            if (val) c_reg[q] = c;
            hval[q] = h;
        }

        if (val) {
#pragma unroll
            for (int q = 0; q < NKK; q++) s_c[tid * NKK + q] = c_reg[q];
            if (tid < 8 || tid >= 120) {
                __stcg((float4*)&g_c[wr][H][bb][kk0],
                       make_float4(c_reg[0], c_reg[1], c_reg[2], c_reg[3]));
                __stcg((float4*)&g_c[wr][H][bb][kk0 + 4],
                       make_float4(c_reg[4], c_reg[5], c_reg[6], c_reg[7]));
            }
            unsigned hu[NKK], lu[NKK];
#pragma unroll
            for (int q = 0; q < NKK; q++) {
                __nv_bfloat16 bh = __float2bfloat16(hval[q]);
                __nv_bfloat16 bl = __float2bfloat16(hval[q] - __bfloat162float(bh));
                hu[q] = (unsigned)__bfloat16_as_ushort(bh);
                lu[q] = (unsigned)__bfloat16_as_ushort(bl);
            }
            __stcg((uint4*)&g_hhi[wr][H][bb][kk0],
                   make_uint4(hu[0]|(hu[1]<<16), hu[2]|(hu[3]<<16),
                              hu[4]|(hu[5]<<16), hu[6]|(hu[7]<<16)));
            __stcg((uint4*)&g_hlo[wr][H][bb][kk0],
                   make_uint4(lu[0]|(lu[1]<<16), lu[2]|(lu[3]<<16),
                              lu[4]|(lu[5]<<16), lu[6]|(lu[7]<<16)));
#pragma unroll
            for (int q = 0; q < NKK; q++)
                atomicAdd(&g_feat[bb][W][kk0 + q], hval[q]);
        }

        gbar(d, bg);
    }
}

// ---------------------------------------------------------------------------
// FC + log-softmax (validated R8 version).
// ---------------------------------------------------------------------------
#define FCW 8
#define FC_SMEM ((HIDc*Vc + FCW*HIDc) * 4)
__global__ __launch_bounds__(128)
void fc_kernel(const float* __restrict__ W_fc, const float* __restrict__ b_fc)
{
    extern __shared__ float fsm[];
    float* s_wfc = fsm;
    float* s_f   = fsm + HIDc * Vc;

    const int wt = blockIdx.x, b = blockIdx.y, tid = threadIdx.x;
    const int wid = tid >> 5, lid = tid & 31;

    for (int i = tid; i < HIDc * Vc; i += 128) s_wfc[i] = W_fc[i];
    for (int i = tid; i < FCW * HIDc; i += 128)
        s_f[i] = g_feat[b][wt * FCW + (i >> 7)][i & 127];
    __syncthreads();

    for (int ws = 0; ws < 2; ws++) {
        const int wloc = wid * 2 + ws;
        const int w = wt * FCW + wloc;
        const float* f = s_f + wloc * HIDc;
        float lg[4];
#pragma unroll
        for (int i = 0; i < 4; i++) {
            int col = lid + 32 * i;
            float a = (col < Vc) ? b_fc[col] : NEGF;
            if (col < Vc) {
#pragma unroll 8
                for (int k = 0; k < HIDc; k++)
                    a = fmaf(f[k], s_wfc[k * Vc + col], a);
            }
            lg[i] = a;
        }
        float m = fmaxf(fmaxf(lg[0], lg[1]), fmaxf(lg[2], lg[3]));
#pragma unroll
        for (int o = 16; o > 0; o >>= 1)
            m = fmaxf(m, __shfl_xor_sync(0xffffffff, m, o));
        float s = 0.f;
#pragma unroll
        for (int i = 0; i < 4; i++) s += __expf(lg[i] - m);
#pragma unroll
        for (int o = 16; o > 0; o >>= 1)
            s += __shfl_xor_sync(0xffffffff, s, o);
        float lse = m + __logf(s);
#pragma unroll
        for (int i = 0; i < 4; i++) {
            int col = lid + 32 * i;
            if (col < Vc) g_logp[b][w][col] = lg[i] - lse;
        }
    }
}

// ---------------------------------------------------------------------------
// CTC alpha: one warp per batch (validated R8 version).
// ---------------------------------------------------------------------------
__global__ __launch_bounds__(32)
void ctc_kernel(const int* __restrict__ y, float* __restrict__ out)
{
    const int b = blockIdx.x, l = threadIdx.x;
    const int lbl = y[b * LBLc + l];
    const int lblp = __shfl_up_sync(0xffffffffu, lbl, 1);
    const bool sk = (l > 0) && (lbl != lblp);
    const float* lp = &g_logp[b][0][0];

    float a0 = (l == 0) ? lp[Vc - 1] : NEGF;
    float a1 = (l == 0) ? lp[lbl]    : NEGF;
    float a2 = NEGF;

    float pb[2], py[2];
    pb[0] = __ldcg(&lp[Vc * 1 + (Vc - 1)]);  py[0] = __ldcg(&lp[Vc * 1 + lbl]);
    pb[1] = __ldcg(&lp[Vc * 2 + (Vc - 1)]);  py[1] = __ldcg(&lp[Vc * 2 + lbl]);

    for (int t = 1; t < Tc; t++) {
        const float lpb = pb[0], lpy = py[0];
        pb[0] = pb[1]; py[0] = py[1];
        if (t + 2 < Tc) {
            pb[1] = __ldcg(&lp[Vc * (t + 2) + (Vc - 1)]);
            py[1] = __ldcg(&lp[Vc * (t + 2) + lbl]);
        }
        float pa1 = __shfl_up_sync(0xffffffffu, a1, 1);
        if (l == 0) pa1 = NEGF;

        float m0 = fmaxf(a0, pa1);
        float n0 = m0 + __logf(__expf(a0 - m0) + __expf(pa1 - m0)) + lpb;

        float s2 = sk ? pa1 : NEGF;
        float m1 = fmaxf(a1, fmaxf(a0, s2));
        float n1 = m1 + __logf(__expf(a1 - m1) + __expf(a0 - m1) +
                               __expf(s2 - m1)) + lpy;

        float n2 = a2;
        if (l == 31) {
            float m2 = fmaxf(a2, a1);
            n2 = m2 + __logf(__expf(a2 - m2) + __expf(a1 - m2)) + lpb;
        }
        a0 = n0; a1 = n1; a2 = n2;
    }

    if (l == 31) {
        float m = fmaxf(a2, a1);
        out[b] = -(m + __logf(__expf(a2 - m) + __expf(a1 - m)));
    }
}

extern "C" void kernel_launch(void* const* d_in, const int* in_sizes, int n_in,
                              void* d_out, int out_size)
{
    const float* X    = (const float*)d_in[0];
    const int*   y    = (const int*)  d_in[1];
    const float* Wx   = (const float*)d_in[2];
    const float* Wh1  = (const float*)d_in[3];
    const float* Wh2  = (const float*)d_in[4];
    const float* bias = (const float*)d_in[5];
    const float* W_fc = (const float*)d_in[6];
    const float* b_fc = (const float*)d_in[7];
    float* out = (float*)d_out;

    cudaFuncSetAttribute(mdlstm_persist,
                         cudaFuncAttributeMaxDynamicSharedMemorySize, SMEM_TOTAL);
    cudaFuncSetAttribute(fc_kernel,
                         cudaFuncAttributeMaxDynamicSharedMemorySize, FC_SMEM);

    init_kernel<<<256, 256>>>();
    mdlstm_persist<<<NCTA, NTHR, SMEM_TOTAL>>>(X, Wx, Wh1, Wh2, bias);
    fc_kernel<<<dim3(Tc / FCW, Bc), 128, FC_SMEM>>>(W_fc, b_fc);
    ctc_kernel<<<Bc, 32>>>(y, out);
}

// round 12
// speedup vs baseline: 1.5499x; 1.5499x over previous
#include <cuda_runtime.h>
#include <math.h>

#define Bc   32
#define Tc   256
#define Fc   32
#define HIDc 128
#define ZW   640
#define Vc   101
#define LBLc 32
#define NEGF (-1e30f)

#define NCTA 128
#define NTHR 256
#define WSTRIDE 2564                 // per-cg weight stride in floats (16B-aligned)
#define HSTRIDE 258                  // per-row dup-h stride (8B-aligned, conflict-free)
#define SW_FLOATS (8*WSTRIDE)        // 20512
#define SH_FLOATS (72*HSTRIDE)       // 18576
#define SC_FLOATS (2*8*64*2)         // 2048
#define SMEM_BYTES ((SW_FLOATS+SH_FLOATS+SC_FLOATS)*4)

// ---------------------------------------------------------------------------
// Device scratch.
// ---------------------------------------------------------------------------
__device__ __align__(16) float g_h[2][Fc][Bc][HIDc];
__device__ __align__(16) float g_c[2][Fc][Bc][HIDc];
__device__ __align__(16) float g_feat[Bc][Tc][HIDc];
__device__ __align__(16) float g_logp[Bc][Tc][Vc];
__device__ unsigned g_cnt4[4 * 32];
__device__ unsigned g_gen4[4 * 32];

__device__ __forceinline__ float fsig(float x) {
    return __fdividef(1.0f, 1.0f + __expf(-x));
}
__device__ __forceinline__ float ftanh(float x) {
    return 1.0f - __fdividef(2.0f, __expf(2.0f * x) + 1.0f);
}

__device__ __forceinline__ unsigned long long pack2f(float lo, float hi) {
    unsigned long long r;
    asm("mov.b64 %0, {%1, %2};" : "=l"(r) : "f"(lo), "f"(hi));
    return r;
}
__device__ __forceinline__ void unpack2f(unsigned long long v, float& lo, float& hi) {
    asm("mov.b64 {%0, %1}, %2;" : "=f"(lo), "=f"(hi) : "l"(v));
}
__device__ __forceinline__ unsigned long long fma2(unsigned long long a,
                                                   unsigned long long b,
                                                   unsigned long long c) {
    unsigned long long d;
    asm("fma.rn.f32x2 %0, %1, %2, %3;" : "=l"(d) : "l"(a), "l"(b), "l"(c));
    return d;
}

__global__ void init_kernel() {
    const int nh = 2 * Fc * Bc * HIDc;
    float* ph = &g_h[0][0][0][0];
    float* pc = &g_c[0][0][0][0];
    for (int i = blockIdx.x * blockDim.x + threadIdx.x; i < nh;
         i += gridDim.x * blockDim.x) { ph[i] = 0.0f; pc[i] = 0.0f; }
    const int nf = Bc * Tc * HIDc;
    float* pf = &g_feat[0][0][0];
    for (int i = blockIdx.x * blockDim.x + threadIdx.x; i < nf;
         i += gridDim.x * blockDim.x) pf[i] = 0.0f;
    if (blockIdx.x == 0 && threadIdx.x < 4 * 32) {
        g_cnt4[threadIdx.x] = 0u;
        g_gen4[threadIdx.x] = 0u;
    }
}

// Per-bg grid barrier (32 CTAs).
__device__ __forceinline__ void gbar(int it, int bg) {
    __syncthreads();
    if (threadIdx.x == 0) {
        unsigned* cnt = &g_cnt4[bg * 32];
        unsigned* gen = &g_gen4[bg * 32];
        const unsigned target = (unsigned)(it + 1);
        unsigned old;
        asm volatile("atom.acq_rel.gpu.global.add.u32 %0, [%1], %2;"
                     : "=r"(old) : "l"(cnt), "r"(1u) : "memory");
        if (old == target * 32u - 1u) {
            asm volatile("st.release.gpu.global.u32 [%0], %1;"
                         :: "l"(gen), "r"(target) : "memory");
        } else {
            unsigned cur;
            do {
                asm volatile("ld.acquire.gpu.global.u32 %0, [%1];"
                             : "=r"(cur) : "l"(gen) : "memory");
            } while (cur < target);
        }
    }
    __syncthreads();
}

// ---------------------------------------------------------------------------
// Persistent MDLSTM wavefront (R8 design + vectorized staging + LDS.128 w).
// 128 CTAs = 8 jkb x 4 bg x 4 cgid, 256 threads (2 warps/SMSP).
// Thread (half, cg, rg) owns 2 rows x (2 k-cols x 5 gates); c in regs + smem.
// ---------------------------------------------------------------------------
__global__ __launch_bounds__(NTHR, 1)
void mdlstm_persist(const float* __restrict__ X,
                    const float* __restrict__ Wx,
                    const float* __restrict__ Wh1,
                    const float* __restrict__ Wh2,
                    const float* __restrict__ bias)
{
    extern __shared__ float smem[];
    float* s_w  = smem;                         // [cg][(g*256+k)*2+c]
    float* s_h2 = smem + SW_FLOATS;             // [rr 0..71][k][dup2]
    float* s_c  = smem + SW_FLOATS + SH_FLOATS; // [p][cg][row][2]

    const int tid  = threadIdx.x;
    const int bx   = blockIdx.x;
    const int jkb  = bx & 7;
    const int bg   = (bx >> 3) & 3;
    const int cgid = bx >> 5;

    const int half = tid >> 7;
    const int cg   = (tid >> 4) & 7;
    const int rg   = tid & 15;

    // One-time: recurrent weights into smem.
    for (int i = tid; i < 8 * 5 * 256 * 2; i += NTHR) {
        int c   = i & 1;
        int k   = (i >> 1) & 255;
        int t2  = i >> 9;
        int g   = t2 % 5;
        int cgl = t2 / 5;
        int col = g * HIDc + jkb * 16 + cgl * 2 + c;
        float v = (k < 128) ? Wh1[k * ZW + col] : Wh2[(k - 128) * ZW + col];
        s_w[cgl * WSTRIDE + ((g << 8) + k) * 2 + c] = v;
    }

    const int kk0 = jkb * 16 + cg * 2;
    float wxl[5], wxh[5], bl0[5], bl1[5];
#pragma unroll
    for (int g = 0; g < 5; g++) {
        int col = g * HIDc + kk0;
        wxl[g] = Wx[col];  wxh[g] = Wx[col + 1];
        bl0[g] = bias[col]; bl1[g] = bias[col + 1];
    }

    int rowj[2], cellj[2], bbj[2];
    rowj[0] = rg + 32 * half;
    rowj[1] = rowj[0] + 16;
#pragma unroll
    for (int j = 0; j < 2; j++) {
        cellj[j] = cgid * 8 + (rowj[j] >> 3);
        bbj[j]   = bg * 8 + (rowj[j] & 7);
    }

    const float* wp  = s_w + cg * WSTRIDE;
    const float* up0 = s_h2 + rowj[0] * HSTRIDE;
    const float* up1 = s_h2 + rowj[1] * HSTRIDE;
    const float* lf0 = up0 + 8 * HSTRIDE;
    const float* lf1 = up1 + 8 * HSTRIDE;

    float2 c_reg[2] = {make_float2(0.f, 0.f), make_float2(0.f, 0.f)};

    __syncthreads();

    for (int d = 0; d < Tc + Fc - 1; d++) {
        const int h_lo = (d > Tc - 1) ? d - (Tc - 1) : 0;
        const int h_hi = (d < Fc - 1) ? d : (Fc - 1);
        const int ncells = h_hi - h_lo + 1;
        const int rd = (d + 1) & 1, wr = d & 1;
        const bool regB = (d > Tc - 1);

        bool val[2]; int hh[2], ww[2];
#pragma unroll
        for (int j = 0; j < 2; j++) {
            val[j] = cellj[j] < ncells;
            hh[j]  = h_lo + cellj[j];
            ww[j]  = d - hh[j];
        }

        // Boundary c prefetch (hidden under staging + k-loop).
        float2 cbnd = make_float2(0.f, 0.f);
        if (!regB) {
            if (rowj[0] < 8 && val[0] && hh[0] > 0)
                cbnd = __ldcg((const float2*)&g_c[rd][hh[0] - 1][bbj[0]][kk0]);
        } else {
            if (rowj[1] >= 56 && val[1])
                cbnd = __ldcg((const float2*)&g_c[rd][hh[1]][bbj[1]][kk0]);
        }

        // X prefetch
        float xv[2];
#pragma unroll
        for (int j = 0; j < 2; j++)
            xv[j] = val[j] ? __ldg(&X[bbj[j] * (Tc * Fc) + ww[j] * Fc + hh[j]]) : 0.f;

        // Stage 9 state rows x 8 batches as duplicate pairs.
        // Vectorized: LDG.128 + four 8B-aligned STS.64 (2304 iters / 256 thr).
        for (int i = tid; i < 72 * 32; i += NTHR) {
            int rr  = i >> 5;
            int kq  = (i & 31) << 2;
            int hhs = h_lo + cgid * 8 - 1 + (rr >> 3);
            int bb2 = bg * 8 + (rr & 7);
            float4 v = make_float4(0.f, 0.f, 0.f, 0.f);
            if (hhs >= 0 && hhs < Fc)
                v = __ldcg((const float4*)&g_h[rd][hhs][bb2][kq]);
            float* dst = s_h2 + rr * HSTRIDE + kq * 2;
            *(float2*)(dst)     = make_float2(v.x, v.x);
            *(float2*)(dst + 2) = make_float2(v.y, v.y);
            *(float2*)(dst + 4) = make_float2(v.z, v.z);
            *(float2*)(dst + 6) = make_float2(v.w, v.w);
        }
        __syncthreads();

        unsigned long long acc[2][5];
#pragma unroll
        for (int j = 0; j < 2; j++)
#pragma unroll
            for (int g = 0; g < 5; g++)
                acc[j][g] = pack2f(fmaf(xv[j], wxl[g], bl0[g]),
                                   fmaf(xv[j], wxh[g], bl1[g]));

        // z += h_left @ Wh1 (k = 2*k2, 2*k2+1): weights via LDS.128.
#pragma unroll 2
        for (int k2 = 0; k2 < 64; k2++) {
            ulonglong2 wv[5];
#pragma unroll
            for (int g = 0; g < 5; g++)
                wv[g] = *(const ulonglong2*)(wp + ((g << 8) + 2 * k2) * 2);
            unsigned long long h0a = *(const unsigned long long*)(lf0 + 4 * k2);
            unsigned long long h0b = *(const unsigned long long*)(lf0 + 4 * k2 + 2);
            unsigned long long h1a = *(const unsigned long long*)(lf1 + 4 * k2);
            unsigned long long h1b = *(const unsigned long long*)(lf1 + 4 * k2 + 2);
#pragma unroll
            for (int g = 0; g < 5; g++) {
                acc[0][g] = fma2(wv[g].x, h0a, acc[0][g]);
                acc[1][g] = fma2(wv[g].x, h1a, acc[1][g]);
            }
#pragma unroll
            for (int g = 0; g < 5; g++) {
                acc[0][g] = fma2(wv[g].y, h0b, acc[0][g]);
                acc[1][g] = fma2(wv[g].y, h1b, acc[1][g]);
            }
        }
        // z += h_up @ Wh2 (k = 128 + 2*k2, ...).
#pragma unroll 2
        for (int k2 = 0; k2 < 64; k2++) {
            ulonglong2 wv[5];
#pragma unroll
            for (int g = 0; g < 5; g++)
                wv[g] = *(const ulonglong2*)(wp + ((g << 8) + 128 + 2 * k2) * 2);
            unsigned long long h0a = *(const unsigned long long*)(up0 + 4 * k2);
            unsigned long long h0b = *(const unsigned long long*)(up0 + 4 * k2 + 2);
            unsigned long long h1a = *(const unsigned long long*)(up1 + 4 * k2);
            unsigned long long h1b = *(const unsigned long long*)(up1 + 4 * k2 + 2);
#pragma unroll
            for (int g = 0; g < 5; g++) {
                acc[0][g] = fma2(wv[g].x, h0a, acc[0][g]);
                acc[1][g] = fma2(wv[g].x, h1a, acc[1][g]);
            }
#pragma unroll
            for (int g = 0; g < 5; g++) {
                acc[0][g] = fma2(wv[g].y, h0b, acc[0][g]);
                acc[1][g] = fma2(wv[g].y, h1b, acc[1][g]);
            }
        }

        // Gates (z order: i, g, f1, f2, o).
#pragma unroll
        for (int j = 0; j < 2; j++) {
            if (!val[j]) continue;
            float zi0, zi1, zg0, zg1, za0, za1, zb0, zb1, zo0, zo1;
            unpack2f(acc[j][0], zi0, zi1);
            unpack2f(acc[j][1], zg0, zg1);
            unpack2f(acc[j][2], za0, za1);
            unpack2f(acc[j][3], zb0, zb1);
            unpack2f(acc[j][4], zo0, zo1);
            const int H = hh[j], W = ww[j], B = bbj[j];
            const int row = rowj[j];

            float2 cl, cu;
            if (!regB) {
                cl = c_reg[j];
                if (row >= 8)
                    cu = *(const float2*)&s_c[(((rd * 8 + cg) * 64) + row - 8) * 2];
                else
                    cu = (H > 0) ? cbnd : make_float2(0.f, 0.f);
            } else {
                cu = c_reg[j];
                if (row < 56)
                    cl = *(const float2*)&s_c[(((rd * 8 + cg) * 64) + row + 8) * 2];
                else
                    cl = cbnd;
            }

            float cA = fsig(za0) * cl.x + fsig(zb0) * cu.x + fsig(zi0) * ftanh(zg0);
            float cB = fsig(za1) * cl.y + fsig(zb1) * cu.y + fsig(zi1) * ftanh(zg1);
            float hA = fsig(zo0) * ftanh(cA);
            float hB = fsig(zo1) * ftanh(cB);

            c_reg[j] = make_float2(cA, cB);
            *(float2*)&s_c[(((wr * 8 + cg) * 64) + row) * 2] = make_float2(cA, cB);
            if (row < 8 || row >= 56)
                __stcg((float2*)&g_c[wr][H][B][kk0], make_float2(cA, cB));
            __stcg((float2*)&g_h[wr][H][B][kk0], make_float2(hA, hB));

            atomicAdd(&g_feat[B][W][kk0],     hA);
            atomicAdd(&g_feat[B][W][kk0 + 1], hB);
        }

        gbar(d, bg);
    }
}

// ---------------------------------------------------------------------------
// FC + log-softmax (validated R8 version).
// ---------------------------------------------------------------------------
#define FCW 8
#define FC_SMEM ((HIDc*Vc + FCW*HIDc) * 4)
__global__ __launch_bounds__(128)
void fc_kernel(const float* __restrict__ W_fc, const float* __restrict__ b_fc)
{
    extern __shared__ float fsm[];
    float* s_wfc = fsm;
    float* s_f   = fsm + HIDc * Vc;

    const int wt = blockIdx.x, b = blockIdx.y, tid = threadIdx.x;
    const int wid = tid >> 5, lid = tid & 31;

    for (int i = tid; i < HIDc * Vc; i += 128) s_wfc[i] = W_fc[i];
    for (int i = tid; i < FCW * HIDc; i += 128)
        s_f[i] = g_feat[b][wt * FCW + (i >> 7)][i & 127];
    __syncthreads();

    for (int ws = 0; ws < 2; ws++) {
        const int wloc = wid * 2 + ws;
        const int w = wt * FCW + wloc;
        const float* f = s_f + wloc * HIDc;
        float lg[4];
#pragma unroll
        for (int i = 0; i < 4; i++) {
            int col = lid + 32 * i;
            float a = (col < Vc) ? b_fc[col] : NEGF;
            if (col < Vc) {
#pragma unroll 8
                for (int k = 0; k < HIDc; k++)
                    a = fmaf(f[k], s_wfc[k * Vc + col], a);
            }
            lg[i] = a;
        }
        float m = fmaxf(fmaxf(lg[0], lg[1]), fmaxf(lg[2], lg[3]));
#pragma unroll
        for (int o = 16; o > 0; o >>= 1)
            m = fmaxf(m, __shfl_xor_sync(0xffffffff, m, o));
        float s = 0.f;
#pragma unroll
        for (int i = 0; i < 4; i++) s += __expf(lg[i] - m);
#pragma unroll
        for (int o = 16; o > 0; o >>= 1)
            s += __shfl_xor_sync(0xffffffff, s, o);
        float lse = m + __logf(s);
#pragma unroll
        for (int i = 0; i < 4; i++) {
            int col = lid + 32 * i;
            if (col < Vc) g_logp[b][w][col] = lg[i] - lse;
        }
    }
}

// ---------------------------------------------------------------------------
// CTC alpha: one warp per batch (validated R8 version).
// ---------------------------------------------------------------------------
__global__ __launch_bounds__(32)
void ctc_kernel(const int* __restrict__ y, float* __restrict__ out)
{
    const int b = blockIdx.x, l = threadIdx.x;
    const int lbl = y[b * LBLc + l];
    const int lblp = __shfl_up_sync(0xffffffffu, lbl, 1);
    const bool sk = (l > 0) && (lbl != lblp);
    const float* lp = &g_logp[b][0][0];

    float a0 = (l == 0) ? lp[Vc - 1] : NEGF;
    float a1 = (l == 0) ? lp[lbl]    : NEGF;
    float a2 = NEGF;

    float pb[2], py[2];
    pb[0] = __ldcg(&lp[Vc * 1 + (Vc - 1)]);  py[0] = __ldcg(&lp[Vc * 1 + lbl]);
    pb[1] = __ldcg(&lp[Vc * 2 + (Vc - 1)]);  py[1] = __ldcg(&lp[Vc * 2 + lbl]);

    for (int t = 1; t < Tc; t++) {
        const float lpb = pb[0], lpy = py[0];
        pb[0] = pb[1]; py[0] = py[1];
        if (t + 2 < Tc) {
            pb[1] = __ldcg(&lp[Vc * (t + 2) + (Vc - 1)]);
            py[1] = __ldcg(&lp[Vc * (t + 2) + lbl]);
        }
        float pa1 = __shfl_up_sync(0xffffffffu, a1, 1);
        if (l == 0) pa1 = NEGF;

        float m0 = fmaxf(a0, pa1);
        float n0 = m0 + __logf(__expf(a0 - m0) + __expf(pa1 - m0)) + lpb;

        float s2 = sk ? pa1 : NEGF;
        float m1 = fmaxf(a1, fmaxf(a0, s2));
        float n1 = m1 + __logf(__expf(a1 - m1) + __expf(a0 - m1) +
                               __expf(s2 - m1)) + lpy;

        float n2 = a2;
        if (l == 31) {
            float m2 = fmaxf(a2, a1);
            n2 = m2 + __logf(__expf(a2 - m2) + __expf(a1 - m2)) + lpb;
        }
        a0 = n0; a1 = n1; a2 = n2;
    }

    if (l == 31) {
        float m = fmaxf(a2, a1);
        out[b] = -(m + __logf(__expf(a2 - m) + __expf(a1 - m)));
    }
}

// ---------------------------------------------------------------------------
// Inputs: X, y, Wx, Wh1, Wh2, b, W_fc, b_fc. Output: float[32].
// ---------------------------------------------------------------------------
extern "C" void kernel_launch(void* const* d_in, const int* in_sizes, int n_in,
                              void* d_out, int out_size)
{
    const float* X    = (const float*)d_in[0];
    const int*   y    = (const int*)  d_in[1];
    const float* Wx   = (const float*)d_in[2];
    const float* Wh1  = (const float*)d_in[3];
    const float* Wh2  = (const float*)d_in[4];
    const float* bias = (const float*)d_in[5];
    const float* W_fc = (const float*)d_in[6];
    const float* b_fc = (const float*)d_in[7];
    float* out = (float*)d_out;

    cudaFuncSetAttribute(mdlstm_persist,
                         cudaFuncAttributeMaxDynamicSharedMemorySize, SMEM_BYTES);
    cudaFuncSetAttribute(fc_kernel,
                         cudaFuncAttributeMaxDynamicSharedMemorySize, FC_SMEM);

    init_kernel<<<256, 256>>>();
    mdlstm_persist<<<NCTA, NTHR, SMEM_BYTES>>>(X, Wx, Wh1, Wh2, bias);
    fc_kernel<<<dim3(Tc / FCW, Bc), 128, FC_SMEM>>>(W_fc, b_fc);
    ctc_kernel<<<Bc, 32>>>(y, out);
}